// round 1
// baseline (speedup 1.0000x reference)
#include <cuda_runtime.h>
#include <cstdint>

// out[b, l] = x[b, perm[b, l]]
// x: [B, L] fp32 (trailing dim 1), perm: [B, L] int32, out: [B, L] fp32.
// B = 1024, L = 16384 (read from in_sizes to stay shape-generic).
//
// Pure gather: vector-load perm (int4), scattered 4B gathers from x (L2-resident
// rows), vector-store out (float4).

__global__ void interleave_gather_kernel(const float* __restrict__ x,
                                         const int* __restrict__ perm,
                                         float* __restrict__ out,
                                         int L, long long total_vec) {
    long long v = (long long)blockIdx.x * blockDim.x + threadIdx.x;
    if (v >= total_vec) return;

    long long e = v * 4;                 // element index of first lane
    long long row = e / L;               // L divisible by 4 -> whole int4 in one row
    const float* xrow = x + row * (long long)L;

    int4 p = reinterpret_cast<const int4*>(perm)[v];

    float4 o;
    o.x = __ldg(xrow + p.x);
    o.y = __ldg(xrow + p.y);
    o.z = __ldg(xrow + p.z);
    o.w = __ldg(xrow + p.w);

    reinterpret_cast<float4*>(out)[v] = o;
}

extern "C" void kernel_launch(void* const* d_in, const int* in_sizes, int n_in,
                              void* d_out, int out_size) {
    const float* x   = (const float*)d_in[0];
    const int* perm  = (const int*)d_in[1];
    float* out       = (float*)d_out;

    // in_sizes[0] = B*L (x elements), in_sizes[1] = B*L (perm elements).
    // perm values are row-local indices in [0, L). Infer L from the known shape:
    // B = 1024, L = total / B. Keep it data-driven but matching the problem.
    long long total = (long long)in_sizes[1];
    int B = 1024;
    int L = (int)(total / B);

    long long total_vec = total / 4;
    int threads = 256;
    long long blocks = (total_vec + threads - 1) / threads;

    interleave_gather_kernel<<<(unsigned)blocks, threads>>>(x, perm, out, L, total_vec);
}

// round 2
// speedup vs baseline: 1.8342x; 1.8342x over previous
#include <cuda_runtime.h>
#include <cstdint>

// out[b, l] = x[b, perm[b, l]]
// x: [B, L] fp32, perm: [B, L] int32 (row-local indices), out: [B, L] fp32.
// B = 1024, L = 16384. One CTA per row; the 64KB row is staged in shared
// memory so the random gather becomes LDS (crossbar) instead of divergent
// global LDG (which was L1tex-wavefront-bound at 81% in R1).

__global__ __launch_bounds__(512, 3)
void interleave_smem_kernel(const float* __restrict__ x,
                            const int* __restrict__ perm,
                            float* __restrict__ out,
                            int L) {
    extern __shared__ float srow[];

    long long row = blockIdx.x;
    const float* xrow = x + row * (long long)L;
    const int* prow   = perm + row * (long long)L;
    float* orow       = out + row * (long long)L;

    int nvec = L >> 2;  // L divisible by 4

    // Phase 1: coalesced streaming load of the row into SMEM (float4).
    const float4* x4 = reinterpret_cast<const float4*>(xrow);
    float4* s4 = reinterpret_cast<float4*>(srow);
    for (int i = threadIdx.x; i < nvec; i += blockDim.x) {
        s4[i] = x4[i];
    }
    __syncthreads();

    // Phase 2: coalesced perm load (int4), SMEM gather, coalesced store (float4).
    const int4* p4 = reinterpret_cast<const int4*>(prow);
    float4* o4 = reinterpret_cast<float4*>(orow);
    for (int i = threadIdx.x; i < nvec; i += blockDim.x) {
        int4 p = p4[i];
        float4 o;
        o.x = srow[p.x];
        o.y = srow[p.y];
        o.z = srow[p.z];
        o.w = srow[p.w];
        o4[i] = o;
    }
}

extern "C" void kernel_launch(void* const* d_in, const int* in_sizes, int n_in,
                              void* d_out, int out_size) {
    const float* x   = (const float*)d_in[0];
    const int* perm  = (const int*)d_in[1];
    float* out       = (float*)d_out;

    long long total = (long long)in_sizes[1];
    int B = 1024;
    int L = (int)(total / B);

    size_t smem = (size_t)L * sizeof(float);  // 64 KB
    // Opt in to >48KB dynamic smem (idempotent; safe under graph capture).
    cudaFuncSetAttribute(interleave_smem_kernel,
                         cudaFuncAttributeMaxDynamicSharedMemorySize, (int)smem);

    interleave_smem_kernel<<<B, 512, smem>>>(x, perm, out, L);
}

// round 3
// speedup vs baseline: 1.8470x; 1.0070x over previous
#include <cuda_runtime.h>
#include <cstdint>

// out[b, l] = x[b, perm[b, l]]   (B=1024, L=16384)
// Per-row CTA. Row staged in SMEM via TMA bulk copy (cp.async.bulk) while all
// threads prefetch their perm int4s from GMEM. After the mbarrier flips:
// pure LDS gather + coalesced float4 stores.

#define THREADS 512

__global__ __launch_bounds__(THREADS, 3)
void interleave_tma_kernel(const float* __restrict__ x,
                           const int* __restrict__ perm,
                           float* __restrict__ out,
                           int L) {
    extern __shared__ __align__(16) unsigned char smem_raw[];
    float* srow = reinterpret_cast<float*>(smem_raw);
    uint64_t* mbar_p = reinterpret_cast<uint64_t*>(smem_raw + (size_t)L * sizeof(float));
    uint32_t mbar = (uint32_t)__cvta_generic_to_shared(mbar_p);
    uint32_t sdst = (uint32_t)__cvta_generic_to_shared(srow);

    long long row = blockIdx.x;
    const float* xrow = x + row * (long long)L;
    const int*   prow = perm + row * (long long)L;
    float*       orow = out + row * (long long)L;

    int tid = threadIdx.x;
    unsigned bytes = (unsigned)L * 4u;

    if (tid == 0) {
        asm volatile("mbarrier.init.shared.b64 [%0], %1;"
                     :: "r"(mbar), "r"(1) : "memory");
    }
    __syncthreads();

    if (tid == 0) {
        asm volatile("mbarrier.arrive.expect_tx.shared.b64 _, [%0], %1;"
                     :: "r"(mbar), "r"(bytes) : "memory");
        asm volatile("cp.async.bulk.shared::cta.global.mbarrier::complete_tx::bytes "
                     "[%0], [%1], %2, [%3];"
                     :: "r"(sdst), "l"(xrow), "r"(bytes), "r"(mbar) : "memory");
    }

    // Prefetch all perm indices for this thread while the TMA streams the row.
    // L = 16384 -> nvec = 4096 = 8 * THREADS exactly.
    const int4* p4 = reinterpret_cast<const int4*>(prow);
    int4 p[8];
    #pragma unroll
    for (int j = 0; j < 8; j++) {
        p[j] = p4[tid + j * THREADS];
    }

    // Wait for the row (acquire orders the subsequent smem reads).
    {
        uint32_t done;
        asm volatile(
            "{\n\t.reg .pred P;\n\t"
            "mbarrier.try_wait.parity.acquire.cta.shared::cta.b64 P, [%1], %2;\n\t"
            "selp.b32 %0, 1, 0, P;\n\t}"
            : "=r"(done) : "r"(mbar), "r"(0u) : "memory");
        if (!done) {
            asm volatile(
                "{\n\t.reg .pred P;\n\t"
                "WAIT_%=:\n\t"
                "mbarrier.try_wait.parity.acquire.cta.shared::cta.b64 P, [%0], %1, 0x989680;\n\t"
                "@P bra.uni DONE_%=;\n\t"
                "bra.uni WAIT_%=;\n\t"
                "DONE_%=:\n\t}"
                :: "r"(mbar), "r"(0u) : "memory");
        }
    }

    // Gather from SMEM, store coalesced.
    float4* o4 = reinterpret_cast<float4*>(orow);
    #pragma unroll
    for (int j = 0; j < 8; j++) {
        float4 o;
        o.x = srow[p[j].x];
        o.y = srow[p[j].y];
        o.z = srow[p[j].z];
        o.w = srow[p[j].w];
        o4[tid + j * THREADS] = o;
    }
}

extern "C" void kernel_launch(void* const* d_in, const int* in_sizes, int n_in,
                              void* d_out, int out_size) {
    const float* x   = (const float*)d_in[0];
    const int* perm  = (const int*)d_in[1];
    float* out       = (float*)d_out;

    long long total = (long long)in_sizes[1];
    int B = 1024;
    int L = (int)(total / B);

    size_t smem = (size_t)L * sizeof(float) + 16;  // row + mbarrier
    cudaFuncSetAttribute(interleave_tma_kernel,
                         cudaFuncAttributeMaxDynamicSharedMemorySize, (int)smem);

    interleave_tma_kernel<<<B, THREADS, smem>>>(x, perm, out, L);
}